// round 8
// baseline (speedup 1.0000x reference)
#include <cuda_runtime.h>
#include <cuda_bf16.h>
#include <cstdint>

// ---------------------------------------------------------------------------
// LSTMPointerNet: BS=16, NMEM=256, NQ=63 (T=64), D=512, H=512
// Inputs (metadata order):
//  0 knowledge_state [16,256,512] f32   1 knowledge_num [16] i32 (unused)
//  2 lstm_in [16,63,512] f32            3 init_h [1,512]   4 init_c [1,512]
//  5 init_i [512]                       6 w_ih [2048,512]  7 w_hh [2048,512]
//  8 b_ih [2048]  9 b_hh [2048]  10 attn_wm [512,512]  11 attn_wq [512,512]
// 12 attn_v [512]
// Output: score [16,64,256] f32
//
// ROUND 8 (falsification): R5 vs R7 rel_errs agree to 4.5e-6 despite TF32-
// level arithmetic differences => recurrence is CONTRACTING and the ~1.95e-2
// error is a systematic shared by all prior rounds. This round removes every
// piece of machinery all rounds shared: the persistent grid-barrier LSTM is
// replaced by 64 sequential kernel launches (stream-ordered, per-launch L1
// flush => no custom sync at all), the TB=true GEMM path is deleted (w_ih is
// explicitly transposed), cell state lives in global memory. Plain fp32 +
// libm math everywhere.
// ---------------------------------------------------------------------------

__device__ float g_xcat[1024 * 512];    // [t*16+b][d]
__device__ float g_wihT[512 * 2048];    // w_ih^T  [d][4H]
__device__ float g_xg  [1024 * 2048];   // [t*16+b][4H]  x @ w_ih^T (no bias)
__device__ float g_feat[4096 * 512];    // [b*256+m][h]
__device__ float g_ys  [1024 * 512];    // [b*64+t][h]
__device__ float g_q   [1024 * 512];    // [b*64+t][h]
__device__ float g_h   [2 * 512 * 16];  // double-buffered h, [k][b]
__device__ float g_c   [512 * 16];      // cell state, [k][b]

// ---------------- helpers ---------------------------------------------------

__device__ __forceinline__ float sigm(float x) { return 1.0f / (1.0f + expf(-x)); }

// ---------------- pack x = concat(init_i, lstm_in), seq-first ---------------

__global__ __launch_bounds__(256) void pack_x_kernel(const float* __restrict__ lstm_in,
                                                     const float* __restrict__ init_i) {
    int gid  = blockIdx.x * 256 + threadIdx.x;   // 131072 float4s
    int fidx = gid * 4;
    int row  = fidx >> 9;        // t*16 + b
    int d    = fidx & 511;
    int t = row >> 4, b = row & 15;
    float4 v;
    if (t == 0) v = *(const float4*)&init_i[d];
    else        v = *(const float4*)&lstm_in[(size_t)(b * 63 + (t - 1)) * 512 + d];
    *(float4*)&g_xcat[fidx] = v;
}

// ---------------- transpose w_ih [2048,512] -> w_ihT [512,2048] --------------

__global__ __launch_bounds__(256) void transpose_kernel(const float* __restrict__ in) {
    __shared__ float tile[32][33];
    // in: [2048 rows, 512 cols]; out: [512 rows, 2048 cols]
    int rb = blockIdx.y * 32;   // row base in 'in' (0..2047)
    int cb = blockIdx.x * 32;   // col base in 'in' (0..511)
    int tx = threadIdx.x & 31, ty = threadIdx.x >> 5;   // 32 x 8
#pragma unroll
    for (int i = 0; i < 4; i++)
        tile[ty + i * 8][tx] = in[(size_t)(rb + ty + i * 8) * 512 + cb + tx];
    __syncthreads();
#pragma unroll
    for (int i = 0; i < 4; i++)
        g_wihT[(size_t)(cb + ty + i * 8) * 2048 + rb + tx] = tile[tx][ty + i * 8];
}

// ---------------- init h, c --------------------------------------------------

__global__ __launch_bounds__(256) void init_hc_kernel(const float* __restrict__ init_h,
                                                      const float* __restrict__ init_c) {
    int gid = blockIdx.x * 256 + threadIdx.x;   // 8192 entries
    int k = gid >> 4, b = gid & 15;
    g_h[k * 16 + b] = init_h[k];
    g_c[k * 16 + b] = init_c[k];
}

// ---------------- plain fp32 tiled GEMM (single, TB=false path) --------------
// C[M,N] = A[M,K] @ B[K,N]. 256 threads, 64x64 tile, 4x4/thread.

__global__ __launch_bounds__(256) void sgemm(const float* __restrict__ A,
                                             const float* __restrict__ B,
                                             float* __restrict__ C,
                                             int M, int N, int K) {
    __shared__ float As[16][68];
    __shared__ float Bs[16][68];
    const int tid = threadIdx.x;
    const int tx = tid & 15;
    const int ty = tid >> 4;
    const int m0 = blockIdx.y * 64, n0 = blockIdx.x * 64;

    float acc[4][4];
#pragma unroll
    for (int i = 0; i < 4; i++)
#pragma unroll
        for (int j = 0; j < 4; j++) acc[i][j] = 0.0f;

    for (int k0 = 0; k0 < K; k0 += 16) {
#pragma unroll
        for (int l = 0; l < 4; l++) {
            int e = tid + l * 256;
            int row = e >> 4, kk = e & 15;
            As[kk][row] = A[(size_t)(m0 + row) * K + k0 + kk];
        }
#pragma unroll
        for (int l = 0; l < 4; l++) {
            int e = tid + l * 256;
            int kk = e >> 6, nn = e & 63;
            Bs[kk][nn] = B[(size_t)(k0 + kk) * N + n0 + nn];
        }
        __syncthreads();
#pragma unroll
        for (int k = 0; k < 16; k++) {
            float a[4], bv[4];
#pragma unroll
            for (int i = 0; i < 4; i++) a[i] = As[k][ty * 4 + i];
#pragma unroll
            for (int j = 0; j < 4; j++) bv[j] = Bs[k][tx * 4 + j];
#pragma unroll
            for (int i = 0; i < 4; i++)
#pragma unroll
                for (int j = 0; j < 4; j++)
                    acc[i][j] = fmaf(a[i], bv[j], acc[i][j]);
        }
        __syncthreads();
    }
#pragma unroll
    for (int i = 0; i < 4; i++)
#pragma unroll
        for (int j = 0; j < 4; j++)
            C[(size_t)(m0 + ty * 4 + i) * N + n0 + tx * 4 + j] = acc[i][j];
}

// ---------------- LSTM single step (one kernel launch per t) -----------------
// 128 blocks x 128 threads; block owns h-indices hb..hb+3 (16 gate rows).
// thread = (batch b, row-pair rp): local rows rp and rp+8.
// All cross-step state (h, c) in global memory; inter-launch ordering by the
// stream. No custom synchronization anywhere.

__global__ __launch_bounds__(128) void lstm_step_kernel(int t,
                                                        const float* __restrict__ w_hh,
                                                        const float* __restrict__ b_ih,
                                                        const float* __restrict__ b_hh) {
    __shared__ float hs[16][516];   // [b][k], padded
    __shared__ float gsm[16][17];   // [local gate row][b]

    const int tid = threadIdx.x;
    const int hb  = blockIdx.x * 4;
    const int b   = tid & 15;
    const int rp  = tid >> 4;                    // 0..7
    const int r0 = rp, r1 = rp + 8;
    const int grow0 = (r0 >> 2) * 512 + hb + (r0 & 3);
    const int grow1 = (r1 >> 2) * 512 + hb + (r1 & 3);
    const float* w0 = w_hh + (size_t)grow0 * 512;
    const float* w1 = w_hh + (size_t)grow1 * 512;

    // load h (512 x 16) -> shared transposed [b][k]
    const float* hp = g_h + (t & 1) * 8192;
    for (int idx = tid; idx < 2048; idx += 128) {
        int k = idx >> 2, bq = (idx & 3) * 4;
        float4 v = *(const float4*)(hp + idx * 4);
        hs[bq + 0][k] = v.x;
        hs[bq + 1][k] = v.y;
        hs[bq + 2][k] = v.z;
        hs[bq + 3][k] = v.w;
    }
    __syncthreads();

    const float xg0 = g_xg[t * 32768 + b * 2048 + grow0];
    const float xg1 = g_xg[t * 32768 + b * 2048 + grow1];
    const float bs0 = b_ih[grow0] + b_hh[grow0];
    const float bs1 = b_ih[grow1] + b_hh[grow1];

    float acc0 = 0.0f, acc1 = 0.0f;
#pragma unroll 8
    for (int k = 0; k < 512; k += 4) {
        float4 hv  = *(const float4*)&hs[b][k];
        float4 w0v = *(const float4*)(w0 + k);
        float4 w1v = *(const float4*)(w1 + k);
        acc0 = fmaf(hv.x, w0v.x, acc0);
        acc0 = fmaf(hv.y, w0v.y, acc0);
        acc0 = fmaf(hv.z, w0v.z, acc0);
        acc0 = fmaf(hv.w, w0v.w, acc0);
        acc1 = fmaf(hv.x, w1v.x, acc1);
        acc1 = fmaf(hv.y, w1v.y, acc1);
        acc1 = fmaf(hv.z, w1v.z, acc1);
        acc1 = fmaf(hv.w, w1v.w, acc1);
    }
    gsm[r0][b] = (xg0 + acc0) + bs0;
    gsm[r1][b] = (xg1 + acc1) + bs1;
    __syncthreads();

    if (tid < 64) {
        int jj = tid >> 4, bb = tid & 15;
        float gi = sigm(gsm[jj][bb]);        // gate i (local rows 0..3)
        float gf = sigm(gsm[4 + jj][bb]);    // gate f
        float gg = tanhf(gsm[8 + jj][bb]);   // gate g
        float go = sigm(gsm[12 + jj][bb]);   // gate o
        int ci = (hb + jj) * 16 + bb;
        float c = gf * g_c[ci] + gi * gg;
        g_c[ci] = c;
        float h = go * tanhf(c);
        g_h[((t + 1) & 1) * 8192 + ci] = h;
        g_ys[(size_t)((bb << 6) + t) * 512 + hb + jj] = h;
    }
}

// ---------------- score: out[b][t][m] = sum_h tanh(feat+q) * v --------------

__global__ __launch_bounds__(128) void score_kernel(const float* __restrict__ v,
                                                    float* __restrict__ out) {
    const int b  = blockIdx.y, mg = blockIdx.x;
    const int w  = threadIdx.x >> 5, lane = threadIdx.x & 31;
    const int m  = mg * 4 + w;
    const float* fp = g_feat + (size_t)((b << 8) + m) * 512;

    float4 ff[4], vv[4];
#pragma unroll
    for (int j = 0; j < 4; j++) {
        ff[j] = *(const float4*)&fp[lane * 4 + j * 128];
        vv[j] = *(const float4*)&v[lane * 4 + j * 128];
    }
    for (int t = 0; t < 64; t++) {
        const float* qp = g_q + (size_t)((b << 6) + t) * 512;
        float s = 0.0f;
#pragma unroll
        for (int j = 0; j < 4; j++) {
            float4 qv = __ldg((const float4*)&qp[lane * 4 + j * 128]);
            s += tanhf(ff[j].x + qv.x) * vv[j].x;
            s += tanhf(ff[j].y + qv.y) * vv[j].y;
            s += tanhf(ff[j].z + qv.z) * vv[j].z;
            s += tanhf(ff[j].w + qv.w) * vv[j].w;
        }
#pragma unroll
        for (int off = 16; off; off >>= 1)
            s += __shfl_xor_sync(0xffffffffu, s, off);
        if (lane == 0) out[(size_t)((b << 6) + t) * 256 + m] = s;
    }
}

// ---------------- launch ----------------------------------------------------

extern "C" void kernel_launch(void* const* d_in, const int* in_sizes, int n_in,
                              void* d_out, int out_size) {
    // Defensive: if knowledge_num (index 1) is absent, later indices shift.
    const int o = (n_in == 12) ? 1 : 0;
    const float* ks      = (const float*)d_in[0];
    const float* lstm_in = (const float*)d_in[2 - o];
    const float* init_h  = (const float*)d_in[3 - o];
    const float* init_c  = (const float*)d_in[4 - o];
    const float* init_i  = (const float*)d_in[5 - o];
    const float* w_ih    = (const float*)d_in[6 - o];
    const float* w_hh    = (const float*)d_in[7 - o];
    const float* b_ih    = (const float*)d_in[8 - o];
    const float* b_hh    = (const float*)d_in[9 - o];
    const float* attn_wm = (const float*)d_in[10 - o];
    const float* attn_wq = (const float*)d_in[11 - o];
    const float* attn_v  = (const float*)d_in[12 - o];
    float* out = (float*)d_out;

    void *p_xcat, *p_wihT, *p_xg, *p_feat, *p_ys, *p_q;
    cudaGetSymbolAddress(&p_xcat, g_xcat);
    cudaGetSymbolAddress(&p_wihT, g_wihT);
    cudaGetSymbolAddress(&p_xg,   g_xg);
    cudaGetSymbolAddress(&p_feat, g_feat);
    cudaGetSymbolAddress(&p_ys,   g_ys);
    cudaGetSymbolAddress(&p_q,    g_q);

    // 1) pack x; transpose w_ih; init h/c
    pack_x_kernel<<<512, 256>>>(lstm_in, init_i);
    transpose_kernel<<<dim3(512 / 32, 2048 / 32), 256>>>(w_ih);
    init_hc_kernel<<<32, 256>>>(init_h, init_c);

    // 2) xg = x @ w_ihT   [1024 x 2048]  (bias added in-cell)
    sgemm<<<dim3(2048 / 64, 1024 / 64), 256>>>(
        (const float*)p_xcat, (const float*)p_wihT, (float*)p_xg, 1024, 2048, 512);

    // 3) feat = knowledge_state @ attn_wm  [4096 x 512]
    sgemm<<<dim3(512 / 64, 4096 / 64), 256>>>(
        ks, attn_wm, (float*)p_feat, 4096, 512, 512);

    // 4) LSTM: 64 sequential step launches (stream-ordered, no custom sync)
    for (int t = 0; t < 64; t++)
        lstm_step_kernel<<<128, 128>>>(t, w_hh, b_ih, b_hh);

    // 5) q = ys @ attn_wq  [1024 x 512]
    sgemm<<<dim3(512 / 64, 1024 / 64), 256>>>(
        (const float*)p_ys, attn_wq, (float*)p_q, 1024, 512, 512);

    // 6) score
    score_kernel<<<dim3(64, 16), 128>>>(attn_v, out);
}

// round 9
// speedup vs baseline: 1.2923x; 1.2923x over previous
#include <cuda_runtime.h>
#include <cuda_bf16.h>
#include <cstdint>

// ---------------------------------------------------------------------------
// LSTMPointerNet: BS=16, NMEM=256, NQ=63 (T=64), D=512, H=512
// Output: score [16,64,256] f32
//
// R8 passed (993us, rel_err 2e-7) with: 64-launch LSTM, explicit w_ih
// transpose, TB=false-only GEMM, global cell state. This round keeps that
// verified dataflow and attacks time: f32x2 GEMM (2x FMA/issue), f32x2 LSTM
// step with PDL (programmatic stream serialization) to hide the 64 launch
// gaps, hw-approx tanh in the unamplified score stage.
// ---------------------------------------------------------------------------

__device__ float g_xcat[1024 * 512];    // [t*16+b][d]
__device__ float g_wihT[512 * 2048];    // w_ih^T  [d][4H]
__device__ float g_xg  [1024 * 2048];   // [t*16+b][4H]  x @ w_ih^T (no bias)
__device__ float g_feat[4096 * 512];    // [b*256+m][h]
__device__ float g_ys  [1024 * 512];    // [b*64+t][h]
__device__ float g_q   [1024 * 512];    // [b*64+t][h]
__device__ float g_h   [2 * 512 * 16];  // double-buffered h, [k][b]
__device__ float g_c   [512 * 16];      // cell state, [k][b]

// ---------------- helpers ---------------------------------------------------

__device__ __forceinline__ void fma2(unsigned long long& d,
                                     unsigned long long a,
                                     unsigned long long b) {
    asm("fma.rn.f32x2 %0, %1, %2, %0;" : "+l"(d) : "l"(a), "l"(b));
}
__device__ __forceinline__ unsigned long long pk2(float x) {
    unsigned long long r;
    asm("mov.b64 %0, {%1, %1};" : "=l"(r) : "f"(x));
    return r;
}
__device__ __forceinline__ void unpk(unsigned long long v, float& lo, float& hi) {
    asm("mov.b64 {%0, %1}, %2;" : "=f"(lo), "=f"(hi) : "l"(v));
}
__device__ __forceinline__ float upsum(unsigned long long v) {
    float lo, hi; unpk(v, lo, hi); return lo + hi;
}
__device__ __forceinline__ float sigm(float x) { return 1.0f / (1.0f + expf(-x)); }

// fast tanh: 1 - 2/(exp2(2x*log2e)+1); ~1e-6 abs err; score stage only
__device__ __forceinline__ float tanh_fast(float x) {
    float e, r;
    asm("ex2.approx.f32 %0, %1;" : "=f"(e) : "f"(x * 2.8853900817779268f));
    asm("rcp.approx.f32 %0, %1;" : "=f"(r) : "f"(e + 1.0f));
    return fmaf(-2.0f, r, 1.0f);
}

// ---------------- pack x = concat(init_i, lstm_in), seq-first ---------------

__global__ __launch_bounds__(256) void pack_x_kernel(const float* __restrict__ lstm_in,
                                                     const float* __restrict__ init_i) {
    int gid  = blockIdx.x * 256 + threadIdx.x;   // 131072 float4s
    int fidx = gid * 4;
    int row  = fidx >> 9;        // t*16 + b
    int d    = fidx & 511;
    int t = row >> 4, b = row & 15;
    float4 v;
    if (t == 0) v = *(const float4*)&init_i[d];
    else        v = *(const float4*)&lstm_in[(size_t)(b * 63 + (t - 1)) * 512 + d];
    *(float4*)&g_xcat[fidx] = v;
}

// ---------------- transpose w_ih [2048,512] -> w_ihT [512,2048] --------------

__global__ __launch_bounds__(256) void transpose_kernel(const float* __restrict__ in) {
    __shared__ float tile[32][33];
    int rb = blockIdx.y * 32;
    int cb = blockIdx.x * 32;
    int tx = threadIdx.x & 31, ty = threadIdx.x >> 5;   // 32 x 8
#pragma unroll
    for (int i = 0; i < 4; i++)
        tile[ty + i * 8][tx] = in[(size_t)(rb + ty + i * 8) * 512 + cb + tx];
    __syncthreads();
#pragma unroll
    for (int i = 0; i < 4; i++)
        g_wihT[(size_t)(cb + ty + i * 8) * 2048 + rb + tx] = tile[tx][ty + i * 8];
}

// ---------------- init h, c --------------------------------------------------

__global__ __launch_bounds__(256) void init_hc_kernel(const float* __restrict__ init_h,
                                                      const float* __restrict__ init_c) {
    int gid = blockIdx.x * 256 + threadIdx.x;   // 8192 entries
    int k = gid >> 4, b = gid & 15;
    g_h[k * 16 + b] = init_h[k];
    g_c[k * 16 + b] = init_c[k];
}

// ---------------- f32x2 GEMM: C[M,N] = A[M,K] @ B[K,N] -----------------------
// 128 threads, tile 128x64, 8x8 per thread. Per k-step: 4 LDS.128 + 32 FFMA2.

__global__ __launch_bounds__(128) void gemm_f32x2(const float* __restrict__ A,
                                                  const float* __restrict__ B,
                                                  float* __restrict__ C,
                                                  int M, int N, int K) {
    __shared__ float As[16][132];   // [k][m], stride 132*4=528B (16B-multiple)
    __shared__ float Bs[16][64];    // [k][n]
    cudaGridDependencySynchronize();

    const int tid = threadIdx.x;
    const int tx = tid & 7;         // n-dir
    const int ty = tid >> 3;        // m-dir (0..15)
    const int m0 = blockIdx.y * 128, n0 = blockIdx.x * 64;

    unsigned long long acc[8][4];
#pragma unroll
    for (int i = 0; i < 8; i++)
#pragma unroll
        for (int p = 0; p < 4; p++) acc[i][p] = 0ull;

    for (int k0 = 0; k0 < K; k0 += 16) {
        // A tile 128x16 -> As[k][m]
#pragma unroll
        for (int l = 0; l < 4; l++) {
            int e = tid + l * 128;
            int row = e >> 2, kq = e & 3;
            float4 v = *(const float4*)&A[(size_t)(m0 + row) * K + k0 + kq * 4];
            As[kq * 4 + 0][row] = v.x;
            As[kq * 4 + 1][row] = v.y;
            As[kq * 4 + 2][row] = v.z;
            As[kq * 4 + 3][row] = v.w;
        }
        // B tile 16x64
#pragma unroll
        for (int l = 0; l < 2; l++) {
            int e = tid + l * 128;
            int kr = e >> 4, nq = e & 15;
            *(float4*)&Bs[kr][nq * 4] =
                *(const float4*)&B[(size_t)(k0 + kr) * N + n0 + nq * 4];
        }
        __syncthreads();
#pragma unroll
        for (int k = 0; k < 16; k++) {
            float4 a0 = *(const float4*)&As[k][ty * 8];
            float4 a1 = *(const float4*)&As[k][ty * 8 + 4];
            ulonglong2 blo = *(const ulonglong2*)&Bs[k][tx * 4];
            ulonglong2 bhi = *(const ulonglong2*)&Bs[k][32 + tx * 4];
            float am[8] = {a0.x, a0.y, a0.z, a0.w, a1.x, a1.y, a1.z, a1.w};
#pragma unroll
            for (int i = 0; i < 8; i++) {
                unsigned long long pa = pk2(am[i]);
                fma2(acc[i][0], pa, blo.x);
                fma2(acc[i][1], pa, blo.y);
                fma2(acc[i][2], pa, bhi.x);
                fma2(acc[i][3], pa, bhi.y);
            }
        }
        __syncthreads();
    }
#pragma unroll
    for (int i = 0; i < 8; i++) {
        float* crow = C + (size_t)(m0 + ty * 8 + i) * N;
#pragma unroll
        for (int g = 0; g < 2; g++) {
#pragma unroll
            for (int p = 0; p < 2; p++) {
                int n = n0 + g * 32 + tx * 4 + p * 2;
                float lo, hi;
                unpk(acc[i][g * 2 + p], lo, hi);
                crow[n]     = lo;
                crow[n + 1] = hi;
            }
        }
    }
}

// ---------------- LSTM single step (one launch per t, PDL-chained) -----------
// 128 blocks x 256 threads; block owns h-indices hb..hb+3 (16 gate rows).
// thread = (batch b = tid&15, local row r = tid>>4). xg/bias loaded before
// the grid dependency sync (they do not depend on the previous step).

__global__ __launch_bounds__(256) void lstm_step_kernel(int t,
                                                        const float* __restrict__ w_hh,
                                                        const float* __restrict__ b_ih,
                                                        const float* __restrict__ b_hh) {
    __shared__ float hs[16][516];   // [b][k]; stride 2064B (16B-multiple)
    __shared__ float gsm[16][17];   // [local gate row][b]

    const int tid = threadIdx.x;
    const int hb  = blockIdx.x * 4;
    const int b   = tid & 15;
    const int r   = tid >> 4;                    // 0..15
    const int grow = (r >> 2) * 512 + hb + (r & 3);
    const float* w = w_hh + (size_t)grow * 512;

    // pre-dependency loads (produced before the step chain)
    const float xg = g_xg[t * 32768 + b * 2048 + grow];
    const float bs = b_ih[grow] + b_hh[grow];

    cudaGridDependencySynchronize();

    // load h (512 x 16) -> shared transposed [b][k]
    const float* hp = g_h + (t & 1) * 8192;
    for (int idx = tid; idx < 2048; idx += 256) {
        int k = idx >> 2, bq = (idx & 3) * 4;
        float4 v = *(const float4*)(hp + idx * 4);
        hs[bq + 0][k] = v.x;
        hs[bq + 1][k] = v.y;
        hs[bq + 2][k] = v.z;
        hs[bq + 3][k] = v.w;
    }
    __syncthreads();

    // f32x2 dot, 4 accumulator chains
    unsigned long long a0 = 0, a1 = 0, a2 = 0, a3 = 0;
#pragma unroll 8
    for (int k = 0; k < 512; k += 8) {
        ulonglong2 h0 = *(const ulonglong2*)&hs[b][k];
        ulonglong2 h1 = *(const ulonglong2*)&hs[b][k + 4];
        ulonglong2 w0 = *(const ulonglong2*)(w + k);
        ulonglong2 w1 = *(const ulonglong2*)(w + k + 4);
        fma2(a0, h0.x, w0.x);
        fma2(a1, h0.y, w0.y);
        fma2(a2, h1.x, w1.x);
        fma2(a3, h1.y, w1.y);
    }
    gsm[r][b] = (xg + (upsum(a0) + upsum(a1) + upsum(a2) + upsum(a3))) + bs;
    __syncthreads();

    if (tid < 64) {
        int jj = tid >> 4, bb = tid & 15;
        float gi = sigm(gsm[jj][bb]);        // gate i
        float gf = sigm(gsm[4 + jj][bb]);    // gate f
        float gg = tanhf(gsm[8 + jj][bb]);   // gate g
        float go = sigm(gsm[12 + jj][bb]);   // gate o
        int ci = (hb + jj) * 16 + bb;
        float c = gf * g_c[ci] + gi * gg;
        g_c[ci] = c;
        float h = go * tanhf(c);
        g_h[((t + 1) & 1) * 8192 + ci] = h;
        g_ys[(size_t)((bb << 6) + t) * 512 + hb + jj] = h;
    }
}

// ---------------- score: out[b][t][m] = sum_h tanh(feat+q) * v --------------

__global__ __launch_bounds__(128) void score_kernel(const float* __restrict__ v,
                                                    float* __restrict__ out) {
    cudaGridDependencySynchronize();
    const int b  = blockIdx.y, mg = blockIdx.x;
    const int w  = threadIdx.x >> 5, lane = threadIdx.x & 31;
    const int m  = mg * 4 + w;
    const float* fp = g_feat + (size_t)((b << 8) + m) * 512;

    float4 ff[4], vv[4];
#pragma unroll
    for (int j = 0; j < 4; j++) {
        ff[j] = *(const float4*)&fp[lane * 4 + j * 128];
        vv[j] = *(const float4*)&v[lane * 4 + j * 128];
    }
    for (int t = 0; t < 64; t++) {
        const float* qp = g_q + (size_t)((b << 6) + t) * 512;
        float s = 0.0f;
#pragma unroll
        for (int j = 0; j < 4; j++) {
            float4 qv = __ldg((const float4*)&qp[lane * 4 + j * 128]);
            s += tanh_fast(ff[j].x + qv.x) * vv[j].x;
            s += tanh_fast(ff[j].y + qv.y) * vv[j].y;
            s += tanh_fast(ff[j].z + qv.z) * vv[j].z;
            s += tanh_fast(ff[j].w + qv.w) * vv[j].w;
        }
#pragma unroll
        for (int off = 16; off; off >>= 1)
            s += __shfl_xor_sync(0xffffffffu, s, off);
        if (lane == 0) out[(size_t)((b << 6) + t) * 256 + m] = s;
    }
}

// ---------------- PDL launch helper -----------------------------------------

template <typename F, typename... Args>
static inline void launch_pdl(F f, dim3 grid, dim3 block, Args... args) {
    cudaLaunchConfig_t cfg = {};
    cfg.gridDim = grid;
    cfg.blockDim = block;
    cfg.dynamicSmemBytes = 0;
    cfg.stream = 0;
    cudaLaunchAttribute attr[1];
    attr[0].id = cudaLaunchAttributeProgrammaticStreamSerialization;
    attr[0].val.programmaticStreamSerializationAllowed = 1;
    cfg.attrs = attr;
    cfg.numAttrs = 1;
    cudaLaunchKernelEx(&cfg, f, args...);
}

// ---------------- launch ----------------------------------------------------

extern "C" void kernel_launch(void* const* d_in, const int* in_sizes, int n_in,
                              void* d_out, int out_size) {
    const int o = (n_in == 12) ? 1 : 0;
    const float* ks      = (const float*)d_in[0];
    const float* lstm_in = (const float*)d_in[2 - o];
    const float* init_h  = (const float*)d_in[3 - o];
    const float* init_c  = (const float*)d_in[4 - o];
    const float* init_i  = (const float*)d_in[5 - o];
    const float* w_ih    = (const float*)d_in[6 - o];
    const float* w_hh    = (const float*)d_in[7 - o];
    const float* b_ih    = (const float*)d_in[8 - o];
    const float* b_hh    = (const float*)d_in[9 - o];
    const float* attn_wm = (const float*)d_in[10 - o];
    const float* attn_wq = (const float*)d_in[11 - o];
    const float* attn_v  = (const float*)d_in[12 - o];
    float* out = (float*)d_out;

    void *p_xcat, *p_wihT, *p_xg, *p_feat, *p_ys, *p_q;
    cudaGetSymbolAddress(&p_xcat, g_xcat);
    cudaGetSymbolAddress(&p_wihT, g_wihT);
    cudaGetSymbolAddress(&p_xg,   g_xg);
    cudaGetSymbolAddress(&p_feat, g_feat);
    cudaGetSymbolAddress(&p_ys,   g_ys);
    cudaGetSymbolAddress(&p_q,    g_q);

    // 1) pack x; transpose w_ih; init h/c (read only harness inputs)
    pack_x_kernel<<<512, 256>>>(lstm_in, init_i);
    transpose_kernel<<<dim3(512 / 32, 2048 / 32), 256>>>(w_ih);
    init_hc_kernel<<<32, 256>>>(init_h, init_c);

    // 2) xg = x @ w_ihT   [1024 x 2048]
    launch_pdl(gemm_f32x2, dim3(2048 / 64, 1024 / 128), dim3(128),
               (const float*)p_xcat, (const float*)p_wihT, (float*)p_xg,
               1024, 2048, 512);

    // 3) feat = knowledge_state @ attn_wm  [4096 x 512]
    launch_pdl(gemm_f32x2, dim3(512 / 64, 4096 / 128), dim3(128),
               ks, attn_wm, (float*)p_feat, 4096, 512, 512);

    // 4) LSTM: 64 step launches, PDL-chained to hide launch gaps
    for (int t = 0; t < 64; t++)
        launch_pdl(lstm_step_kernel, dim3(128), dim3(256), t, w_hh, b_ih, b_hh);

    // 5) q = ys @ attn_wq  [1024 x 512]
    launch_pdl(gemm_f32x2, dim3(512 / 64, 1024 / 128), dim3(128),
               (const float*)p_ys, attn_wq, (float*)p_q, 1024, 512, 512);

    // 6) score
    launch_pdl(score_kernel, dim3(64, 16), dim3(128), attn_v, out);
}

// round 12
// speedup vs baseline: 1.3553x; 1.0488x over previous
#include <cuda_runtime.h>
#include <cuda_bf16.h>
#include <cstdint>

// ---------------------------------------------------------------------------
// LSTMPointerNet: BS=16, NMEM=256, NQ=63 (T=64), D=512, H=512
// Output: score [16,64,256] f32
//
// R11 verdict: persistent grid-barrier LSTM fails numerically on this stack
// (6/6 attempts, incl. byte-identical step body) while launch-per-step
// passes (2/2). Persistence abandoned. This round optimizes within the
// launch-based structure: smem-staged w+h in the step kernel, PDL trigger
// for dispatch overlap, poly transcendentals (1 MUFU), register
// double-buffered GEMM.
// ---------------------------------------------------------------------------

__device__ float g_xcat[1024 * 512];    // [t*16+b][d]
__device__ float g_wihT[512 * 2048];    // w_ih^T  [d][4H]
__device__ float g_xg  [1024 * 2048];   // [t*16+b][4H]  x @ w_ih^T (no bias)
__device__ float g_feat[4096 * 512];    // [b*256+m][h]
__device__ float g_ys  [1024 * 512];    // [b*64+t][h]
__device__ float g_q   [1024 * 512];    // [b*64+t][h]
__device__ float g_h   [2 * 512 * 16];  // double-buffered h, [k][b]
__device__ float g_c   [512 * 16];      // cell state, [k][b]

// ---------------- helpers ---------------------------------------------------

__device__ __forceinline__ void fma2(unsigned long long& d,
                                     unsigned long long a,
                                     unsigned long long b) {
    asm("fma.rn.f32x2 %0, %1, %2, %0;" : "+l"(d) : "l"(a), "l"(b));
}
__device__ __forceinline__ unsigned long long pk2(float x) {
    unsigned long long r;
    asm("mov.b64 %0, {%1, %1};" : "=l"(r) : "f"(x));
    return r;
}
__device__ __forceinline__ void unpk(unsigned long long v, float& lo, float& hi) {
    asm("mov.b64 {%0, %1}, %2;" : "=f"(lo), "=f"(hi) : "l"(v));
}
__device__ __forceinline__ float upsum(unsigned long long v) {
    float lo, hi; unpk(v, lo, hi); return lo + hi;
}
__device__ __forceinline__ float4 ldcg4(const float* p) {
    float4 v;
    asm volatile("ld.global.cg.v4.f32 {%0,%1,%2,%3}, [%4];"
                 : "=f"(v.x), "=f"(v.y), "=f"(v.z), "=f"(v.w) : "l"(p));
    return v;
}
__device__ __forceinline__ float rcp_approx(float x) {
    float r;
    asm("rcp.approx.f32 %0, %1;" : "=f"(r) : "f"(x));
    return r;
}

// rational poly tanh (Eigen-style): 1 MUFU (rcp) + ~11 FMA; abs err ~1e-6
__device__ __forceinline__ float tanh_poly(float x) {
    const float kClamp = 7.90531110763549805f;
    float xc = fminf(fmaxf(x, -kClamp), kClamp);
    float x2 = xc * xc;
    float p = fmaf(x2, -2.76076847742355e-16f, 2.00018790482477e-13f);
    p = fmaf(x2, p, -8.60467152213735e-11f);
    p = fmaf(x2, p, 5.12229709037114e-08f);
    p = fmaf(x2, p, 1.48572235717979e-05f);
    p = fmaf(x2, p, 6.37261928875436e-04f);
    p = fmaf(x2, p, 4.89352455891786e-03f);
    p *= xc;
    float q = fmaf(x2, 1.19825839466702e-06f, 1.18534705686654e-04f);
    q = fmaf(x2, q, 2.26843463243900e-03f);
    q = fmaf(x2, q, 4.89352518554385e-03f);
    return p * rcp_approx(q);
}
__device__ __forceinline__ float sigm_poly(float x) {
    return fmaf(0.5f, tanh_poly(0.5f * x), 0.5f);
}

// ---------------- pack x = concat(init_i, lstm_in), seq-first ---------------

__global__ __launch_bounds__(256) void pack_x_kernel(const float* __restrict__ lstm_in,
                                                     const float* __restrict__ init_i) {
    int gid  = blockIdx.x * 256 + threadIdx.x;   // 131072 float4s
    int fidx = gid * 4;
    int row  = fidx >> 9;        // t*16 + b
    int d    = fidx & 511;
    int t = row >> 4, b = row & 15;
    float4 v;
    if (t == 0) v = *(const float4*)&init_i[d];
    else        v = *(const float4*)&lstm_in[(size_t)(b * 63 + (t - 1)) * 512 + d];
    *(float4*)&g_xcat[fidx] = v;
}

// ---------------- transpose w_ih [2048,512] -> w_ihT [512,2048] --------------

__global__ __launch_bounds__(256) void transpose_kernel(const float* __restrict__ in) {
    __shared__ float tile[32][33];
    int rb = blockIdx.y * 32;
    int cb = blockIdx.x * 32;
    int tx = threadIdx.x & 31, ty = threadIdx.x >> 5;   // 32 x 8
#pragma unroll
    for (int i = 0; i < 4; i++)
        tile[ty + i * 8][tx] = in[(size_t)(rb + ty + i * 8) * 512 + cb + tx];
    __syncthreads();
#pragma unroll
    for (int i = 0; i < 4; i++)
        g_wihT[(size_t)(cb + ty + i * 8) * 2048 + rb + tx] = tile[tx][ty + i * 8];
}

// ---------------- init h, c --------------------------------------------------

__global__ __launch_bounds__(256) void init_hc_kernel(const float* __restrict__ init_h,
                                                      const float* __restrict__ init_c) {
    int gid = blockIdx.x * 256 + threadIdx.x;   // 8192 entries
    int k = gid >> 4, b = gid & 15;
    g_h[k * 16 + b] = init_h[k];
    g_c[k * 16 + b] = init_c[k];
}

// ---------------- f32x2 GEMM, register double-buffered -----------------------
// C[M,N] = A[M,K] @ B[K,N]. 128 threads, tile 128x64, 8x8/thread.

__global__ __launch_bounds__(128) void gemm_f32x2(const float* __restrict__ A,
                                                  const float* __restrict__ B,
                                                  float* __restrict__ C,
                                                  int M, int N, int K) {
    __shared__ float As[16][132];
    __shared__ float Bs[16][64];
    const int tid = threadIdx.x;
    const int tx = tid & 7;
    const int ty = tid >> 3;
    const int m0 = blockIdx.y * 128, n0 = blockIdx.x * 64;

    // prelude: compute addresses before the dependency sync
    cudaGridDependencySynchronize();

    unsigned long long acc[8][4];
#pragma unroll
    for (int i = 0; i < 8; i++)
#pragma unroll
        for (int p = 0; p < 4; p++) acc[i][p] = 0ull;

    float4 ra[4], rb[2];
    // preload tile 0
#pragma unroll
    for (int l = 0; l < 4; l++) {
        int e = tid + l * 128;
        int row = e >> 2, kq = e & 3;
        ra[l] = *(const float4*)&A[(size_t)(m0 + row) * K + kq * 4];
    }
#pragma unroll
    for (int l = 0; l < 2; l++) {
        int e = tid + l * 128;
        int kr = e >> 4, nq = e & 15;
        rb[l] = *(const float4*)&B[(size_t)kr * N + n0 + nq * 4];
    }

    for (int k0 = 0; k0 < K; k0 += 16) {
        // store staged tile to smem
#pragma unroll
        for (int l = 0; l < 4; l++) {
            int e = tid + l * 128;
            int row = e >> 2, kq = e & 3;
            As[kq * 4 + 0][row] = ra[l].x;
            As[kq * 4 + 1][row] = ra[l].y;
            As[kq * 4 + 2][row] = ra[l].z;
            As[kq * 4 + 3][row] = ra[l].w;
        }
#pragma unroll
        for (int l = 0; l < 2; l++) {
            int e = tid + l * 128;
            int kr = e >> 4, nq = e & 15;
            *(float4*)&Bs[kr][nq * 4] = rb[l];
        }
        __syncthreads();
        // prefetch next tile while computing this one
        if (k0 + 16 < K) {
#pragma unroll
            for (int l = 0; l < 4; l++) {
                int e = tid + l * 128;
                int row = e >> 2, kq = e & 3;
                ra[l] = *(const float4*)&A[(size_t)(m0 + row) * K + k0 + 16 + kq * 4];
            }
#pragma unroll
            for (int l = 0; l < 2; l++) {
                int e = tid + l * 128;
                int kr = e >> 4, nq = e & 15;
                rb[l] = *(const float4*)&B[(size_t)(k0 + 16 + kr) * N + n0 + nq * 4];
            }
        }
#pragma unroll
        for (int k = 0; k < 16; k++) {
            float4 a0 = *(const float4*)&As[k][ty * 8];
            float4 a1 = *(const float4*)&As[k][ty * 8 + 4];
            ulonglong2 blo = *(const ulonglong2*)&Bs[k][tx * 4];
            ulonglong2 bhi = *(const ulonglong2*)&Bs[k][32 + tx * 4];
            float am[8] = {a0.x, a0.y, a0.z, a0.w, a1.x, a1.y, a1.z, a1.w};
#pragma unroll
            for (int i = 0; i < 8; i++) {
                unsigned long long pa = pk2(am[i]);
                fma2(acc[i][0], pa, blo.x);
                fma2(acc[i][1], pa, blo.y);
                fma2(acc[i][2], pa, bhi.x);
                fma2(acc[i][3], pa, bhi.y);
            }
        }
        __syncthreads();
    }
    // allow the dependent kernel to start dispatching during our epilogue
    cudaTriggerProgrammaticLaunchCompletion();
#pragma unroll
    for (int i = 0; i < 8; i++) {
        float* crow = C + (size_t)(m0 + ty * 8 + i) * N;
#pragma unroll
        for (int g = 0; g < 2; g++) {
#pragma unroll
            for (int p = 0; p < 2; p++) {
                int n = n0 + g * 32 + tx * 4 + p * 2;
                float lo, hi;
                unpk(acc[i][g * 2 + p], lo, hi);
                crow[n]     = lo;
                crow[n + 1] = hi;
            }
        }
    }
}

// ---------------- LSTM single step (launch per t, PDL trigger) ---------------
// 128 blocks x 256 threads; block owns h-indices hb..hb+3 (16 gate rows).
// thread = (batch b = tid&15, local row r = tid>>4). w slice (32KB) and h
// (32KB) are cooperatively staged into dynamic smem with coalesced high-MLP
// LDG.cg; the dot then runs LDS/FFMA2-bound. Trigger fires after staging so
// the next step's dispatch overlaps our dot+tail.

extern __shared__ float s_dyn[];   // [0:16*516) hs | [16*516:2*16*516) ws

__global__ __launch_bounds__(256) void lstm_step_kernel(int t,
                                                        const float* __restrict__ w_hh,
                                                        const float* __restrict__ b_ih,
                                                        const float* __restrict__ b_hh) {
    __shared__ float gsm[16][17];   // [local gate row][b]
    float* hs = s_dyn;              // [b][k], stride 516
    float* ws = s_dyn + 16 * 516;   // [r][k], stride 516

    const int tid = threadIdx.x;
    const int hb  = blockIdx.x * 4;
    const int b   = tid & 15;
    const int r   = tid >> 4;                    // 0..15
    const int grow = (r >> 2) * 512 + hb + (r & 3);

    // prelude (inputs independent of the previous step)
    const float xg = g_xg[t * 32768 + b * 2048 + grow];
    const float bs = b_ih[grow] + b_hh[grow];
    // w staging addresses (local row -> global row)
    int widx[8], wrow[8];
#pragma unroll
    for (int i = 0; i < 8; i++) {
        int e = tid + i * 256;          // 0..2047 float4s
        wrow[i] = e >> 7;               // local row 0..15
        widx[i] = e & 127;              // float4 within row
    }

    cudaGridDependencySynchronize();

    // stage h (L2-coherent) and w (coalesced) into smem
    const float* hp = g_h + (t & 1) * 8192;
#pragma unroll
    for (int i = 0; i < 8; i++) {
        int idx = tid + i * 256;        // 2048 float4s
        int k = idx >> 2, bq = (idx & 3) * 4;
        float4 v = ldcg4(hp + idx * 4);
        hs[(bq + 0) * 516 + k] = v.x;
        hs[(bq + 1) * 516 + k] = v.y;
        hs[(bq + 2) * 516 + k] = v.z;
        hs[(bq + 3) * 516 + k] = v.w;
    }
#pragma unroll
    for (int i = 0; i < 8; i++) {
        int lr = wrow[i];
        int gr = (lr >> 2) * 512 + hb + (lr & 3);
        float4 v = ldcg4(&w_hh[(size_t)gr * 512 + widx[i] * 4]);
        *(float4*)&ws[lr * 516 + widx[i] * 4] = v;
    }
    __syncthreads();

    // let the next step start its dispatch + prelude now
    cudaTriggerProgrammaticLaunchCompletion();

    // f32x2 dot, 4 accumulator chains, all-smem operands
    const float* hrow = hs + b * 516;
    const float* wrw  = ws + r * 516;
    unsigned long long a0 = 0, a1 = 0, a2 = 0, a3 = 0;
#pragma unroll 8
    for (int k = 0; k < 512; k += 8) {
        ulonglong2 h0 = *(const ulonglong2*)(hrow + k);
        ulonglong2 h1 = *(const ulonglong2*)(hrow + k + 4);
        ulonglong2 w0 = *(const ulonglong2*)(wrw + k);
        ulonglong2 w1 = *(const ulonglong2*)(wrw + k + 4);
        fma2(a0, h0.x, w0.x);
        fma2(a1, h0.y, w0.y);
        fma2(a2, h1.x, w1.x);
        fma2(a3, h1.y, w1.y);
    }
    gsm[r][b] = (xg + (upsum(a0) + upsum(a1) + upsum(a2) + upsum(a3))) + bs;
    __syncthreads();

    if (tid < 64) {
        int jj = tid >> 4, bb = tid & 15;
        float gi = sigm_poly(gsm[jj][bb]);        // gate i
        float gf = sigm_poly(gsm[4 + jj][bb]);    // gate f
        float gg = tanh_poly(gsm[8 + jj][bb]);    // gate g
        float go = sigm_poly(gsm[12 + jj][bb]);   // gate o
        int ci = (hb + jj) * 16 + bb;
        float c = gf * g_c[ci] + gi * gg;
        g_c[ci] = c;
        float h = go * tanh_poly(c);
        g_h[((t + 1) & 1) * 8192 + ci] = h;
        g_ys[(size_t)((bb << 6) + t) * 512 + hb + jj] = h;
    }
}

// ---------------- score: out[b][t][m] = sum_h tanh(feat+q) * v --------------

__global__ __launch_bounds__(128) void score_kernel(const float* __restrict__ v,
                                                    float* __restrict__ out) {
    cudaGridDependencySynchronize();
    const int b  = blockIdx.y, mg = blockIdx.x;
    const int w  = threadIdx.x >> 5, lane = threadIdx.x & 31;
    const int m  = mg * 4 + w;
    const float* fp = g_feat + (size_t)((b << 8) + m) * 512;

    float4 ff[4], vv[4];
#pragma unroll
    for (int j = 0; j < 4; j++) {
        ff[j] = *(const float4*)&fp[lane * 4 + j * 128];
        vv[j] = *(const float4*)&v[lane * 4 + j * 128];
    }
    for (int t = 0; t < 64; t++) {
        const float* qp = g_q + (size_t)((b << 6) + t) * 512;
        float s = 0.0f;
#pragma unroll
        for (int j = 0; j < 4; j++) {
            float4 qv = __ldg((const float4*)&qp[lane * 4 + j * 128]);
            s += tanh_poly(ff[j].x + qv.x) * vv[j].x;
            s += tanh_poly(ff[j].y + qv.y) * vv[j].y;
            s += tanh_poly(ff[j].z + qv.z) * vv[j].z;
            s += tanh_poly(ff[j].w + qv.w) * vv[j].w;
        }
#pragma unroll
        for (int off = 16; off; off >>= 1)
            s += __shfl_xor_sync(0xffffffffu, s, off);
        if (lane == 0) out[(size_t)((b << 6) + t) * 256 + m] = s;
    }
}

// ---------------- PDL launch helper -----------------------------------------

template <typename F, typename... Args>
static inline void launch_pdl(F f, dim3 grid, dim3 block, size_t smem, Args... args) {
    cudaLaunchConfig_t cfg = {};
    cfg.gridDim = grid;
    cfg.blockDim = block;
    cfg.dynamicSmemBytes = smem;
    cfg.stream = 0;
    cudaLaunchAttribute attr[1];
    attr[0].id = cudaLaunchAttributeProgrammaticStreamSerialization;
    attr[0].val.programmaticStreamSerializationAllowed = 1;
    cfg.attrs = attr;
    cfg.numAttrs = 1;
    cudaLaunchKernelEx(&cfg, f, args...);
}

// ---------------- launch ----------------------------------------------------

extern "C" void kernel_launch(void* const* d_in, const int* in_sizes, int n_in,
                              void* d_out, int out_size) {
    const int o = (n_in == 12) ? 1 : 0;
    const float* ks      = (const float*)d_in[0];
    const float* lstm_in = (const float*)d_in[2 - o];
    const float* init_h  = (const float*)d_in[3 - o];
    const float* init_c  = (const float*)d_in[4 - o];
    const float* init_i  = (const float*)d_in[5 - o];
    const float* w_ih    = (const float*)d_in[6 - o];
    const float* w_hh    = (const float*)d_in[7 - o];
    const float* b_ih    = (const float*)d_in[8 - o];
    const float* b_hh    = (const float*)d_in[9 - o];
    const float* attn_wm = (const float*)d_in[10 - o];
    const float* attn_wq = (const float*)d_in[11 - o];
    const float* attn_v  = (const float*)d_in[12 - o];
    float* out = (float*)d_out;

    void *p_xcat, *p_wihT, *p_xg, *p_feat, *p_ys, *p_q;
    cudaGetSymbolAddress(&p_xcat, g_xcat);
    cudaGetSymbolAddress(&p_wihT, g_wihT);
    cudaGetSymbolAddress(&p_xg,   g_xg);
    cudaGetSymbolAddress(&p_feat, g_feat);
    cudaGetSymbolAddress(&p_ys,   g_ys);
    cudaGetSymbolAddress(&p_q,    g_q);

    const size_t lstm_smem = 2 * 16 * 516 * sizeof(float);   // 66048 B
    cudaFuncSetAttribute(lstm_step_kernel,
                         cudaFuncAttributeMaxDynamicSharedMemorySize,
                         (int)lstm_smem);

    // 1) prep (plain launches)
    pack_x_kernel<<<512, 256>>>(lstm_in, init_i);
    transpose_kernel<<<dim3(512 / 32, 2048 / 32), 256>>>(w_ih);
    init_hc_kernel<<<32, 256>>>(init_h, init_c);

    // 2) xg = x @ w_ihT   [1024 x 2048]
    launch_pdl(gemm_f32x2, dim3(2048 / 64, 1024 / 128), dim3(128), 0,
               (const float*)p_xcat, (const float*)p_wihT, (float*)p_xg,
               1024, 2048, 512);

    // 3) feat = knowledge_state @ attn_wm  [4096 x 512]
    launch_pdl(gemm_f32x2, dim3(512 / 64, 4096 / 128), dim3(128), 0,
               ks, attn_wm, (float*)p_feat, 4096, 512, 512);

    // 4) LSTM: 64 step launches (PDL attr + in-kernel trigger overlap)
    for (int t = 0; t < 64; t++)
        launch_pdl(lstm_step_kernel, dim3(128), dim3(256), lstm_smem,
                   t, w_hh, b_ih, b_hh);

    // 5) q = ys @ attn_wq  [1024 x 512]
    launch_pdl(gemm_f32x2, dim3(512 / 64, 1024 / 128), dim3(128), 0,
               (const float*)p_ys, attn_wq, (float*)p_q, 1024, 512, 512);

    // 6) score
    launch_pdl(score_kernel, dim3(64, 16), dim3(128), 0, attn_v, out);
}